// round 3
// baseline (speedup 1.0000x reference)
#include <cuda_runtime.h>
#include <math.h>
#include <stdint.h>

// ---------------- problem constants ----------------
#define QLEN   4096          // H*W
#define NFR    6             // N frames
#define GRP    8             // G groups
#define DIMC   256           // DIM
#define HEADS  4
#define DH     64
#define NKEY   48            // NFR*GRP
#define R_TOT  (NFR*QLEN)    // 24576 rows (n,q)
#define EPSLN  1e-5f
#define SCALE  0.125f        // DH^-0.5

// ---------------- scratch (static device memory; no allocations) ----------------
__device__ float g_qln [R_TOT*DIMC];     // LN'd transposed q          25 MB
__device__ float g_qp  [R_TOT*DIMC];     // q projection               25 MB
__device__ float g_t   [R_TOT*1024];     // t[r][m][c]                100 MB
__device__ float g_wkT [DIMC*DIMC];      // wk transposed
__device__ float g_dot [QLEN*HEADS*NKEY];// scores -> att (in place)
__device__ float g_apre[QLEN*1024];      // per-head weighted LN(v) sums
__device__ float g_av  [QLEN*DIMC];      // attention output rows
__device__ float g_zp  [QLEN*DIMC];      // proj output
__device__ float g_zln [QLEN*DIMC];      // LN_pre(z)
__device__ float g_h1  [QLEN*512];       // mlp hidden
__device__ float g_hp  [QLEN*DIMC];      // mlp output
__device__ int   g_mmode;                // 0=uint8, 1=int32, 2=float32
__device__ float g_maskf[R_TOT];         // normalized mask (1.0 keep / 0.0 drop)

// ---------------- helpers ----------------
__device__ __forceinline__ void blockReduce2(float& s1, float& s2, float* red)
{
    // blockDim.x == 256 (8 warps). red: shared float[16]
    int lane = threadIdx.x & 31, w = threadIdx.x >> 5;
#pragma unroll
    for (int o = 16; o > 0; o >>= 1) {
        s1 += __shfl_xor_sync(0xffffffffu, s1, o);
        s2 += __shfl_xor_sync(0xffffffffu, s2, o);
    }
    if (lane == 0) { red[w] = s1; red[8 + w] = s2; }
    __syncthreads();
    float a = 0.f, b = 0.f;
#pragma unroll
    for (int j = 0; j < 8; j++) { a += red[j]; b += red[8 + j]; }
    s1 = a; s2 = b;
    __syncthreads();
}

// ---------------- K0a: detect mask dtype from byte signature ----------------
// Safe: inspects only the first NFR*QLEN bytes, which exist under every
// candidate layout (uint8 needs 24576 B; int32/float32 buffers are 98304 B).
__global__ void k_mask_detect(const unsigned char* __restrict__ m)
{
    __shared__ int fA, fB;
    if (threadIdx.x == 0) { fA = 0; fB = 0; }
    __syncthreads();
    for (int i = threadIdx.x; i < NFR * QLEN; i += 256) {
        unsigned char b = m[i];
        if (b == 1) {
            if ((i & 3) == 0) fA = 1;   // lsb byte of an int32 {0,1}, or a bool byte
            else              fB = 1;   // only possible for packed uint8 bools
        }
    }
    __syncthreads();
    if (threadIdx.x == 0) {
        // uint8 bool: random 1-bytes at all alignments -> fB set.
        // int32 {0,1}: 1-bytes only at i%4==0 -> fA set, fB clear.
        // float32 {0.f,1.f}: bytes are {0x00,0x80,0x3F}, never 0x01 -> both clear.
        g_mmode = fB ? 0 : (fA ? 1 : 2);
    }
}

// ---------------- K0b: normalize mask to float ----------------
__global__ void k_mask_norm(const void* __restrict__ m)
{
    int i = blockIdx.x * 256 + threadIdx.x;
    if (i >= NFR * QLEN) return;
    int mode = g_mmode;
    float r;
    if (mode == 0)      r = (((const unsigned char*)m)[i] != 0) ? 1.f : 0.f;
    else if (mode == 1) r = (((const int*)m)[i] != 0) ? 1.f : 0.f;
    else                r = (((const float*)m)[i] != 0.f) ? 1.f : 0.f;
    g_maskf[i] = r;
}

// ---------------- K1: transpose q (n,c,p)->(r=nq, c) + LayerNorm ----------------
__global__ __launch_bounds__(256)
void k_q_ln(const float* __restrict__ q, const float* __restrict__ g,
            const float* __restrict__ b, float* __restrict__ out)
{
    __shared__ float tile[256][33];
    __shared__ float s_mu[32], s_rs[32];
    __shared__ float s_part[2][8][32];
    int n  = blockIdx.y;
    int p0 = blockIdx.x * 32;
    int t  = threadIdx.x;
    int px = t & 31, cy = t >> 5;
    const float* qn = q + (size_t)n * DIMC * QLEN;
    float s1 = 0.f, s2 = 0.f;
    for (int c = cy; c < DIMC; c += 8) {
        float v = qn[(size_t)c * QLEN + p0 + px];
        tile[c][px] = v;
        s1 += v; s2 += v * v;
    }
    s_part[0][cy][px] = s1; s_part[1][cy][px] = s2;
    __syncthreads();
    if (cy == 0) {
        float a = 0.f, bb = 0.f;
#pragma unroll
        for (int j = 0; j < 8; j++) { a += s_part[0][j][px]; bb += s_part[1][j][px]; }
        float mu = a * (1.f / 256.f);
        float var = bb * (1.f / 256.f) - mu * mu;
        s_mu[px] = mu; s_rs[px] = rsqrtf(var + EPSLN);
    }
    __syncthreads();
    float gg = g[t], bv = b[t];
    float* orow = out + ((size_t)n * QLEN + p0) * DIMC;
#pragma unroll 4
    for (int pp = 0; pp < 32; pp++) {
        float v = tile[t][pp];
        orow[(size_t)pp * DIMC + t] = (v - s_mu[pp]) * s_rs[pp] * gg + bv;
    }
}

// ---------------- K2: 256x256 transpose (for wk) ----------------
__global__ void k_tr256(const float* __restrict__ w, float* __restrict__ wt)
{
    __shared__ float tile[32][33];
    int bx = blockIdx.x * 32, by = blockIdx.y * 32;
    int x = threadIdx.x, y = threadIdx.y;   // block (32,8)
    for (int j = 0; j < 32; j += 8) tile[y + j][x] = w[(size_t)(by + y + j) * 256 + bx + x];
    __syncthreads();
    for (int j = 0; j < 32; j += 8) wt[(size_t)(bx + y + j) * 256 + by + x] = tile[x][y + j];
}

// ---------------- K3: fp32 tiled GEMM  C[MxN] = A[MxK] @ B[KxN] (+bias)(+gelu) ----------------
__global__ __launch_bounds__(256)
void sgemm(int M, int N, int K,
           const float* __restrict__ A, int lda,
           const float* __restrict__ B, int ldb,
           const float* __restrict__ bias,
           float* __restrict__ C, int ldc, int act)
{
    const int BM = 128, BN = 128, BK = 8;
    __shared__ float As[BK][BM];
    __shared__ float Bs[BK][BN];
    int tid = threadIdx.x;
    int bm = blockIdx.y * BM, bn = blockIdx.x * BN;
    int arow = tid >> 1, acol = (tid & 1) << 2;
    int brow = tid >> 5, bcol = (tid & 31) << 2;
    int ty = (tid >> 4) << 3;
    int tx = (tid & 15) << 3;
    float acc[8][8] = {};
    const float* Aptr = A + (size_t)(bm + arow) * lda + acol;
    const float* Bptr = B + (size_t)brow * ldb + bn + bcol;
    bool aval = (bm + arow) < M;
    bool bval = (bn + bcol) < N;
    for (int k0 = 0; k0 < K; k0 += BK) {
        float4 av = make_float4(0.f, 0.f, 0.f, 0.f);
        float4 bv = make_float4(0.f, 0.f, 0.f, 0.f);
        if (aval) av = *(const float4*)(Aptr + k0);
        if (bval) bv = *(const float4*)(Bptr + (size_t)k0 * ldb);
        As[acol + 0][arow] = av.x;
        As[acol + 1][arow] = av.y;
        As[acol + 2][arow] = av.z;
        As[acol + 3][arow] = av.w;
        *(float4*)&Bs[brow][bcol] = bv;
        __syncthreads();
#pragma unroll
        for (int kk = 0; kk < BK; kk++) {
            float4 a0 = *(const float4*)&As[kk][ty];
            float4 a1 = *(const float4*)&As[kk][ty + 4];
            float4 b0 = *(const float4*)&Bs[kk][tx];
            float4 b1 = *(const float4*)&Bs[kk][tx + 4];
            float ar[8] = {a0.x, a0.y, a0.z, a0.w, a1.x, a1.y, a1.z, a1.w};
            float br[8] = {b0.x, b0.y, b0.z, b0.w, b1.x, b1.y, b1.z, b1.w};
#pragma unroll
            for (int i = 0; i < 8; i++)
#pragma unroll
                for (int j = 0; j < 8; j++)
                    acc[i][j] += ar[i] * br[j];
        }
        __syncthreads();
    }
#pragma unroll
    for (int i = 0; i < 8; i++) {
        int row = bm + ty + i;
        if (row >= M) continue;
#pragma unroll
        for (int j = 0; j < 8; j++) {
            int col = bn + tx + j;
            if (col < N) {
                float v = acc[i][j] + (bias ? bias[col] : 0.f);
                if (act == 1) v = 0.5f * v * (1.f + erff(v * 0.70710678118654752f));
                C[(size_t)row * ldc + col] = v;
            }
        }
    }
}

// ---------------- K4: attention scores. CTA per (n,q): 8 warps = 8 groups ----------------
__global__ __launch_bounds__(256)
void k_dot(const float* __restrict__ kten, const float* __restrict__ qp,
           const float* __restrict__ tg, const float* __restrict__ bk,
           const float* __restrict__ lng, const float* __restrict__ lnb,
           const float* __restrict__ maskf, float* __restrict__ dotp)
{
    int r = blockIdx.x;              // n*QLEN + q
    int n = r >> 12, q = r & 4095;
    int tid = threadIdx.x, lane = tid & 31, w = tid >> 5;
    __shared__ float ts[1024];
    __shared__ float bd[4];
    __shared__ float sg[256], sb[256];
    const float* trow = tg + (size_t)r * 1024;
#pragma unroll
    for (int i = 0; i < 4; i++) ts[tid + 256 * i] = trow[tid + 256 * i];
    sg[tid] = lng[tid]; sb[tid] = lnb[tid];
    if (w < 4) {
        const float* qpr = qp + (size_t)r * 256 + w * 64;
        const float* bkr = bk + w * 64;
        float p = qpr[lane] * bkr[lane] + qpr[lane + 32] * bkr[lane + 32];
#pragma unroll
        for (int o = 16; o > 0; o >>= 1) p += __shfl_xor_sync(0xffffffffu, p, o);
        if (lane == 0) bd[w] = p;
    }
    __syncthreads();
    // warp w -> group g = w
    const float* krow = kten + ((size_t)r * GRP + w) * 256;
    float v[8];
    float s1 = 0.f, s2 = 0.f;
#pragma unroll
    for (int j = 0; j < 8; j++) {
        v[j] = krow[lane + 32 * j];
        s1 += v[j]; s2 += v[j] * v[j];
    }
#pragma unroll
    for (int o = 16; o > 0; o >>= 1) {
        s1 += __shfl_xor_sync(0xffffffffu, s1, o);
        s2 += __shfl_xor_sync(0xffffffffu, s2, o);
    }
    float mu = s1 * (1.f / 256.f);
    float rs = rsqrtf(s2 * (1.f / 256.f) - mu * mu + EPSLN);
    float d0 = 0.f, d1 = 0.f, d2 = 0.f, d3 = 0.f;
#pragma unroll
    for (int j = 0; j < 8; j++) {
        int c = lane + 32 * j;
        float lv = (v[j] - mu) * rs * sg[c] + sb[c];
        d0 += lv * ts[c];
        d1 += lv * ts[256 + c];
        d2 += lv * ts[512 + c];
        d3 += lv * ts[768 + c];
    }
#pragma unroll
    for (int o = 16; o > 0; o >>= 1) {
        d0 += __shfl_xor_sync(0xffffffffu, d0, o);
        d1 += __shfl_xor_sync(0xffffffffu, d1, o);
        d2 += __shfl_xor_sync(0xffffffffu, d2, o);
        d3 += __shfl_xor_sync(0xffffffffu, d3, o);
    }
    if (lane == 0) {
        bool mk = maskf[r] != 0.f;
        float dm[4] = {d0, d1, d2, d3};
        size_t base = (size_t)q * (HEADS * NKEY) + (size_t)n * GRP + w;
#pragma unroll
        for (int m = 0; m < 4; m++)
            dotp[base + (size_t)m * NKEY] = mk ? SCALE * (dm[m] + bd[m]) : -1e9f;
    }
}

// ---------------- K5: softmax over 48 keys; one warp per (q,m) row ----------------
__global__ __launch_bounds__(256)
void k_softmax(float* __restrict__ d)
{
    int row = blockIdx.x * 8 + (threadIdx.x >> 5);  // q*4+m, 16384 rows
    int lane = threadIdx.x & 31;
    float* p = d + (size_t)row * NKEY;
    float v0 = p[lane];
    float v1 = (lane < 16) ? p[32 + lane] : -3.4e38f;
    float m = fmaxf(v0, v1);
#pragma unroll
    for (int o = 16; o > 0; o >>= 1) m = fmaxf(m, __shfl_xor_sync(0xffffffffu, m, o));
    float e0 = expf(v0 - m);
    float e1 = (lane < 16) ? expf(v1 - m) : 0.f;
    float s = e0 + e1;
#pragma unroll
    for (int o = 16; o > 0; o >>= 1) s += __shfl_xor_sync(0xffffffffu, s, o);
    float inv = 1.f / s;
    p[lane] = e0 * inv;
    if (lane < 16) p[32 + lane] = e1 * inv;
}

// ---------------- K6: weighted sum of LN(v) rows per head. CTA per q ----------------
__global__ __launch_bounds__(256)
void k_vacc(const float* __restrict__ vten, const float* __restrict__ att,
            const float* __restrict__ lng, const float* __restrict__ lnb,
            float* __restrict__ apre)
{
    __shared__ float sa[HEADS * NKEY];
    __shared__ float red[16];
    int q = blockIdx.x, c = threadIdx.x;
    if (c < HEADS * NKEY) sa[c] = att[(size_t)q * (HEADS * NKEY) + c];
    float gg = lng[c], bb = lnb[c];
    float a0 = 0.f, a1 = 0.f, a2 = 0.f, a3 = 0.f;
    __syncthreads();
    for (int kk = 0; kk < NKEY; kk++) {
        int n = kk >> 3, g = kk & 7;
        float v = vten[(((size_t)n * QLEN + q) * GRP + g) * 256 + c];
        float s1 = v, s2 = v * v;
        blockReduce2(s1, s2, red);
        float mu = s1 * (1.f / 256.f);
        float rs = rsqrtf(s2 * (1.f / 256.f) - mu * mu + EPSLN);
        float lv = (v - mu) * rs * gg + bb;
        a0 += sa[kk] * lv;
        a1 += sa[NKEY + kk] * lv;
        a2 += sa[2 * NKEY + kk] * lv;
        a3 += sa[3 * NKEY + kk] * lv;
    }
    float* o = apre + (size_t)q * 1024 + c;
    o[0] = a0; o[256] = a1; o[512] = a2; o[768] = a3;
}

// ---------------- K7: z = LN_pre(zp + skip^T) ----------------
__global__ __launch_bounds__(256)
void k_ln_skip(const float* __restrict__ zp, const float* __restrict__ skip,
               const float* __restrict__ g, const float* __restrict__ b,
               float* __restrict__ zln)
{
    __shared__ float red[16];
    int q = blockIdx.x, c = threadIdx.x;
    float v = zp[(size_t)q * 256 + c] + skip[(size_t)c * QLEN + q];
    float s1 = v, s2 = v * v;
    blockReduce2(s1, s2, red);
    float mu = s1 * (1.f / 256.f);
    float rs = rsqrtf(s2 * (1.f / 256.f) - mu * mu + EPSLN);
    zln[(size_t)q * 256 + c] = (v - mu) * rs * g[c] + b[c];
}

// ---------------- K8: out = LN_post(zln + hp), written transposed (c,p) ----------------
__global__ __launch_bounds__(256)
void k_ln_out(const float* __restrict__ zln, const float* __restrict__ hp,
              const float* __restrict__ g, const float* __restrict__ b,
              float* __restrict__ out)
{
    __shared__ float red[16];
    int q = blockIdx.x, c = threadIdx.x;
    float v = zln[(size_t)q * 256 + c] + hp[(size_t)q * 256 + c];
    float s1 = v, s2 = v * v;
    blockReduce2(s1, s2, red);
    float mu = s1 * (1.f / 256.f);
    float rs = rsqrtf(s2 * (1.f / 256.f) - mu * mu + EPSLN);
    out[(size_t)c * QLEN + q] = (v - mu) * rs * g[c] + b[c];
}

// ---------------- host launch ----------------
extern "C" void kernel_launch(void* const* d_in, const int* in_sizes, int n_in,
                              void* d_out, int out_size)
{
    const float* q        = (const float*)d_in[0];
    const float* k        = (const float*)d_in[1];
    const float* v        = (const float*)d_in[2];
    const float* skip     = (const float*)d_in[3];
    const void*  mask     = d_in[4];
    const float* ln_q_g   = (const float*)d_in[5];
    const float* ln_q_b   = (const float*)d_in[6];
    const float* wq       = (const float*)d_in[7];
    const float* bq       = (const float*)d_in[8];
    const float* ln_k_g   = (const float*)d_in[9];
    const float* ln_k_b   = (const float*)d_in[10];
    const float* wk       = (const float*)d_in[11];
    const float* bk       = (const float*)d_in[12];
    const float* ln_v_g   = (const float*)d_in[13];
    const float* ln_v_b   = (const float*)d_in[14];
    const float* wv       = (const float*)d_in[15];
    const float* bv       = (const float*)d_in[16];
    const float* w_proj   = (const float*)d_in[17];
    const float* b_proj   = (const float*)d_in[18];
    const float* ln_pre_g = (const float*)d_in[19];
    const float* ln_pre_b = (const float*)d_in[20];
    const float* w_mlp1   = (const float*)d_in[21];
    const float* b_mlp1   = (const float*)d_in[22];
    const float* w_mlp2   = (const float*)d_in[23];
    const float* b_mlp2   = (const float*)d_in[24];
    const float* ln_post_g= (const float*)d_in[25];
    const float* ln_post_b= (const float*)d_in[26];
    float* out = (float*)d_out;

    float *qln, *qp, *t, *wkT, *dot, *apre, *av, *zp, *zln, *h1, *hp, *maskf;
    cudaGetSymbolAddress((void**)&qln,  g_qln);
    cudaGetSymbolAddress((void**)&qp,   g_qp);
    cudaGetSymbolAddress((void**)&t,    g_t);
    cudaGetSymbolAddress((void**)&wkT,  g_wkT);
    cudaGetSymbolAddress((void**)&dot,  g_dot);
    cudaGetSymbolAddress((void**)&apre, g_apre);
    cudaGetSymbolAddress((void**)&av,   g_av);
    cudaGetSymbolAddress((void**)&zp,   g_zp);
    cudaGetSymbolAddress((void**)&zln,  g_zln);
    cudaGetSymbolAddress((void**)&h1,   g_h1);
    cudaGetSymbolAddress((void**)&hp,   g_hp);
    cudaGetSymbolAddress((void**)&maskf,g_maskf);

    // 0. mask dtype detect + normalize
    k_mask_detect<<<1, 256>>>((const unsigned char*)mask);
    k_mask_norm<<<(NFR * QLEN + 255) / 256, 256>>>(mask);
    // 1. q transpose + LN
    k_q_ln<<<dim3(QLEN / 32, NFR), 256>>>(q, ln_q_g, ln_q_b, qln);
    // 2. wk transpose
    k_tr256<<<dim3(8, 8), dim3(32, 8)>>>(wk, wkT);
    // 3. qp = qln @ wq + bq    (24576 x 256 x 256)
    sgemm<<<dim3(2, 192), 256>>>(R_TOT, 256, 256, qln, 256, wq, 256, bq, qp, 256, 0);
    // 4. t_m = qp_m @ wk_m^T   (24576 x 256, K=64, per head)
    for (int m = 0; m < HEADS; m++)
        sgemm<<<dim3(2, 192), 256>>>(R_TOT, 256, 64, qp + m * 64, 256,
                                     wkT + (size_t)m * 64 * 256, 256, nullptr,
                                     t + m * 256, 1024, 0);
    // 5. attention scores (incl. LN(k), bias term, mask, scale)
    k_dot<<<R_TOT, 256>>>(k, qp, t, bk, ln_k_g, ln_k_b, maskf, dot);
    // 6. softmax over 48 keys
    k_softmax<<<QLEN * HEADS / 8, 256>>>(dot);
    // 7. per-head attention-weighted sums of LN(v)
    k_vacc<<<QLEN, 256>>>(v, dot, ln_v_g, ln_v_b, apre);
    // 8. a_m = apre_m @ wv_m + bv_m   (4096 x 64 x 256, per head)
    for (int m = 0; m < HEADS; m++)
        sgemm<<<dim3(1, 32), 256>>>(QLEN, 64, 256, apre + m * 256, 1024,
                                    wv + m * 64, 256, bv + m * 64, av + m * 64, 256, 0);
    // 9. zp = a @ w_proj + b_proj
    sgemm<<<dim3(2, 32), 256>>>(QLEN, 256, 256, av, 256, w_proj, 256, b_proj, zp, 256, 0);
    // 10. z = LN_pre(zp + skip)
    k_ln_skip<<<QLEN, 256>>>(zp, skip, ln_pre_g, ln_pre_b, zln);
    // 11. h1 = gelu(z @ w_mlp1 + b_mlp1)
    sgemm<<<dim3(4, 32), 256>>>(QLEN, 512, 256, zln, 256, w_mlp1, 512, b_mlp1, h1, 512, 1);
    // 12. hp = h1 @ w_mlp2 + b_mlp2
    sgemm<<<dim3(2, 32), 256>>>(QLEN, 256, 512, h1, 512, w_mlp2, 256, b_mlp2, hp, 256, 0);
    // 13. out = LN_post(z + hp), transposed store
    k_ln_out<<<QLEN, 256>>>(zln, hp, ln_post_g, ln_post_b, out);
}

// round 4
// speedup vs baseline: 2.1834x; 2.1834x over previous
#include <cuda_runtime.h>
#include <math.h>
#include <stdint.h>

// ---------------- problem constants ----------------
#define QLEN   4096
#define NFR    6
#define GRP    8
#define DIMC   256
#define HEADS  4
#define DH     64
#define NKEY   48
#define R_TOT  (NFR*QLEN)
#define EPSLN  1e-5f
#define SCALE  0.125f

// ---------------- scratch ----------------
__device__ float g_qln [R_TOT*DIMC];
__device__ float g_qp  [R_TOT*DIMC];
__device__ float g_t   [R_TOT*1024];
__device__ float g_wkT [DIMC*DIMC];
__device__ float g_dot [QLEN*HEADS*NKEY];
__device__ float g_apre[QLEN*1024];
__device__ float g_av  [QLEN*DIMC];
__device__ float g_zp  [QLEN*DIMC];
__device__ float g_zln [QLEN*DIMC];
__device__ float g_h1  [QLEN*512];
__device__ float g_hp  [QLEN*DIMC];
__device__ int   g_mmode;
__device__ float g_maskf[R_TOT];

// ---------------- helpers ----------------
__device__ __forceinline__ void blockReduce2(float& s1, float& s2, float* red)
{
    int lane = threadIdx.x & 31, w = threadIdx.x >> 5;
#pragma unroll
    for (int o = 16; o > 0; o >>= 1) {
        s1 += __shfl_xor_sync(0xffffffffu, s1, o);
        s2 += __shfl_xor_sync(0xffffffffu, s2, o);
    }
    if (lane == 0) { red[w] = s1; red[8 + w] = s2; }
    __syncthreads();
    float a = 0.f, b = 0.f;
#pragma unroll
    for (int j = 0; j < 8; j++) { a += red[j]; b += red[8 + j]; }
    s1 = a; s2 = b;
    __syncthreads();
}

__device__ __forceinline__ void split_tf32(float v, uint32_t& hi, uint32_t& lo)
{
    uint32_t h;
    asm("cvt.rna.tf32.f32 %0, %1;" : "=r"(h) : "f"(v));
    float r = v - __uint_as_float(h);
    uint32_t l;
    asm("cvt.rna.tf32.f32 %0, %1;" : "=r"(l) : "f"(r));
    hi = h; lo = l;
}

__device__ __forceinline__ void mma8(float* c, const uint32_t* a, const uint32_t* b)
{
    asm volatile(
        "mma.sync.aligned.m16n8k8.row.col.f32.tf32.tf32.f32 "
        "{%0,%1,%2,%3}, {%4,%5,%6,%7}, {%8,%9}, {%0,%1,%2,%3};"
        : "+f"(c[0]), "+f"(c[1]), "+f"(c[2]), "+f"(c[3])
        : "r"(a[0]), "r"(a[1]), "r"(a[2]), "r"(a[3]), "r"(b[0]), "r"(b[1]));
}

// ---------------- mask dtype detect + normalize ----------------
__global__ void k_mask_detect(const unsigned char* __restrict__ m)
{
    __shared__ int fA, fB;
    if (threadIdx.x == 0) { fA = 0; fB = 0; }
    __syncthreads();
    for (int i = threadIdx.x; i < NFR * QLEN; i += 256) {
        unsigned char b = m[i];
        if (b == 1) {
            if ((i & 3) == 0) fA = 1;
            else              fB = 1;
        }
    }
    __syncthreads();
    if (threadIdx.x == 0) g_mmode = fB ? 0 : (fA ? 1 : 2);
}

__global__ void k_mask_norm(const void* __restrict__ m)
{
    int i = blockIdx.x * 256 + threadIdx.x;
    if (i >= NFR * QLEN) return;
    int mode = g_mmode;
    float r;
    if (mode == 0)      r = (((const unsigned char*)m)[i] != 0) ? 1.f : 0.f;
    else if (mode == 1) r = (((const int*)m)[i] != 0) ? 1.f : 0.f;
    else                r = (((const float*)m)[i] != 0.f) ? 1.f : 0.f;
    g_maskf[i] = r;
}

// ---------------- K1: transpose q + LayerNorm ----------------
__global__ __launch_bounds__(256)
void k_q_ln(const float* __restrict__ q, const float* __restrict__ g,
            const float* __restrict__ b, float* __restrict__ out)
{
    __shared__ float tile[256][33];
    __shared__ float s_mu[32], s_rs[32];
    __shared__ float s_part[2][8][32];
    int n  = blockIdx.y;
    int p0 = blockIdx.x * 32;
    int t  = threadIdx.x;
    int px = t & 31, cy = t >> 5;
    const float* qn = q + (size_t)n * DIMC * QLEN;
    float s1 = 0.f, s2 = 0.f;
    for (int c = cy; c < DIMC; c += 8) {
        float v = qn[(size_t)c * QLEN + p0 + px];
        tile[c][px] = v;
        s1 += v; s2 += v * v;
    }
    s_part[0][cy][px] = s1; s_part[1][cy][px] = s2;
    __syncthreads();
    if (cy == 0) {
        float a = 0.f, bb = 0.f;
#pragma unroll
        for (int j = 0; j < 8; j++) { a += s_part[0][j][px]; bb += s_part[1][j][px]; }
        float mu = a * (1.f / 256.f);
        float var = bb * (1.f / 256.f) - mu * mu;
        s_mu[px] = mu; s_rs[px] = rsqrtf(var + EPSLN);
    }
    __syncthreads();
    float gg = g[t], bv = b[t];
    float* orow = out + ((size_t)n * QLEN + p0) * DIMC;
#pragma unroll 4
    for (int pp = 0; pp < 32; pp++) {
        float v = tile[t][pp];
        orow[(size_t)pp * DIMC + t] = (v - s_mu[pp]) * s_rs[pp] * gg + bv;
    }
}

// ---------------- K2: 256x256 transpose ----------------
__global__ void k_tr256(const float* __restrict__ w, float* __restrict__ wt)
{
    __shared__ float tile[32][33];
    int bx = blockIdx.x * 32, by = blockIdx.y * 32;
    int x = threadIdx.x, y = threadIdx.y;
    for (int j = 0; j < 32; j += 8) tile[y + j][x] = w[(size_t)(by + y + j) * 256 + bx + x];
    __syncthreads();
    for (int j = 0; j < 32; j += 8) wt[(size_t)(bx + y + j) * 256 + by + x] = tile[x][y + j];
}

// ---------------- tf32 tensor-core GEMM (3xTF32, fp32-accurate) ----------------
// C[M,N] = A[M,K] @ B[K,N] (+bias)(+gelu). M%128==0, K%32==0, N%64==0 assumed.
// blockIdx.z batches with element offsets aoz/boz/coz/bioz.
__global__ __launch_bounds__(256)
void tgemm(int M, int N, int K,
           const float* __restrict__ A, int lda, long aoz,
           const float* __restrict__ B, int ldb, long boz,
           const float* __restrict__ bias, int bioz,
           float* __restrict__ C, int ldc, long coz, int act)
{
    __shared__ float As[128][36];   // [m][k], pad 4: frag banks 4g+t distinct
    __shared__ float Bs[32][136];   // [k][n], pad 8: frag banks 8t+g distinct

    int z = blockIdx.z;
    A += (size_t)z * aoz;
    B += (size_t)z * boz;
    C += (size_t)z * coz;
    if (bias) bias += (size_t)z * bioz;

    int tid = threadIdx.x, lane = tid & 31, wid = tid >> 5;
    int wm = wid & 3, wn = wid >> 2;       // warps 4(M) x 2(N)
    int g = lane >> 2, t = lane & 3;
    int bm = blockIdx.y * 128, bn = blockIdx.x * 128;

    float acc[2][8][4] = {};

    int arow = tid >> 3;                   // 0..31
    int acol = (tid & 7) << 2;             // 0..28
    int bcol = lane << 2;                  // 0..124

    for (int k0 = 0; k0 < K; k0 += 32) {
        // fill As (row copy, float4)
#pragma unroll
        for (int p = 0; p < 4; p++) {
            int m = p * 32 + arow;
            float4 v = *(const float4*)(A + (size_t)(bm + m) * lda + k0 + acol);
            *(float4*)&As[m][acol] = v;
        }
        // fill Bs (row copy, float4), zero-pad n >= N
#pragma unroll
        for (int p = 0; p < 4; p++) {
            int kk = p * 8 + wid;
            float4 v = make_float4(0.f, 0.f, 0.f, 0.f);
            if (bn + bcol < N)
                v = *(const float4*)(B + (size_t)(k0 + kk) * ldb + bn + bcol);
            *(float4*)&Bs[kk][bcol] = v;
        }
        __syncthreads();

#pragma unroll
        for (int ks = 0; ks < 4; ks++) {
            int kb = ks * 8;
            uint32_t ahi[2][4], alo[2][4];
#pragma unroll
            for (int i = 0; i < 2; i++) {
                int mr = wm * 32 + i * 16 + g;
                float x0 = As[mr][kb + t];
                float x1 = As[mr + 8][kb + t];
                float x2 = As[mr][kb + t + 4];
                float x3 = As[mr + 8][kb + t + 4];
                split_tf32(x0, ahi[i][0], alo[i][0]);
                split_tf32(x1, ahi[i][1], alo[i][1]);
                split_tf32(x2, ahi[i][2], alo[i][2]);
                split_tf32(x3, ahi[i][3], alo[i][3]);
            }
#pragma unroll
            for (int j = 0; j < 8; j++) {
                int nc = wn * 64 + j * 8 + g;
                float y0 = Bs[kb + t][nc];
                float y1 = Bs[kb + t + 4][nc];
                uint32_t bhi[2], blo[2];
                split_tf32(y0, bhi[0], blo[0]);
                split_tf32(y1, bhi[1], blo[1]);
#pragma unroll
                for (int i = 0; i < 2; i++) {
                    mma8(acc[i][j], ahi[i], bhi);
                    mma8(acc[i][j], alo[i], bhi);
                    mma8(acc[i][j], ahi[i], blo);
                }
            }
        }
        __syncthreads();
    }

    // epilogue
#pragma unroll
    for (int i = 0; i < 2; i++) {
        int r0 = bm + wm * 32 + i * 16 + g;
#pragma unroll
        for (int j = 0; j < 8; j++) {
            int c0 = bn + wn * 64 + j * 8 + t * 2;
            if (c0 < N) {
                float b0v = bias ? bias[c0] : 0.f;
                float b1v = bias ? bias[c0 + 1] : 0.f;
                float v0 = acc[i][j][0] + b0v;
                float v1 = acc[i][j][1] + b1v;
                float v2 = acc[i][j][2] + b0v;
                float v3 = acc[i][j][3] + b1v;
                if (act == 1) {
                    v0 = 0.5f * v0 * (1.f + erff(v0 * 0.70710678118654752f));
                    v1 = 0.5f * v1 * (1.f + erff(v1 * 0.70710678118654752f));
                    v2 = 0.5f * v2 * (1.f + erff(v2 * 0.70710678118654752f));
                    v3 = 0.5f * v3 * (1.f + erff(v3 * 0.70710678118654752f));
                }
                *(float2*)&C[(size_t)r0 * ldc + c0] = make_float2(v0, v1);
                *(float2*)&C[(size_t)(r0 + 8) * ldc + c0] = make_float2(v2, v3);
            }
        }
    }
}

// ---------------- K4: attention scores ----------------
__global__ __launch_bounds__(256)
void k_dot(const float* __restrict__ kten, const float* __restrict__ qp,
           const float* __restrict__ tg, const float* __restrict__ bk,
           const float* __restrict__ lng, const float* __restrict__ lnb,
           const float* __restrict__ maskf, float* __restrict__ dotp)
{
    int r = blockIdx.x;
    int n = r >> 12, q = r & 4095;
    int tid = threadIdx.x, lane = tid & 31, w = tid >> 5;
    __shared__ float ts[1024];
    __shared__ float bd[4];
    __shared__ float sg[256], sb[256];
    const float* trow = tg + (size_t)r * 1024;
#pragma unroll
    for (int i = 0; i < 4; i++) ts[tid + 256 * i] = trow[tid + 256 * i];
    sg[tid] = lng[tid]; sb[tid] = lnb[tid];
    if (w < 4) {
        const float* qpr = qp + (size_t)r * 256 + w * 64;
        const float* bkr = bk + w * 64;
        float p = qpr[lane] * bkr[lane] + qpr[lane + 32] * bkr[lane + 32];
#pragma unroll
        for (int o = 16; o > 0; o >>= 1) p += __shfl_xor_sync(0xffffffffu, p, o);
        if (lane == 0) bd[w] = p;
    }
    __syncthreads();
    const float* krow = kten + ((size_t)r * GRP + w) * 256;
    float v[8];
    float s1 = 0.f, s2 = 0.f;
#pragma unroll
    for (int j = 0; j < 8; j++) {
        v[j] = krow[lane + 32 * j];
        s1 += v[j]; s2 += v[j] * v[j];
    }
#pragma unroll
    for (int o = 16; o > 0; o >>= 1) {
        s1 += __shfl_xor_sync(0xffffffffu, s1, o);
        s2 += __shfl_xor_sync(0xffffffffu, s2, o);
    }
    float mu = s1 * (1.f / 256.f);
    float rs = rsqrtf(s2 * (1.f / 256.f) - mu * mu + EPSLN);
    float d0 = 0.f, d1 = 0.f, d2 = 0.f, d3 = 0.f;
#pragma unroll
    for (int j = 0; j < 8; j++) {
        int c = lane + 32 * j;
        float lv = (v[j] - mu) * rs * sg[c] + sb[c];
        d0 += lv * ts[c];
        d1 += lv * ts[256 + c];
        d2 += lv * ts[512 + c];
        d3 += lv * ts[768 + c];
    }
#pragma unroll
    for (int o = 16; o > 0; o >>= 1) {
        d0 += __shfl_xor_sync(0xffffffffu, d0, o);
        d1 += __shfl_xor_sync(0xffffffffu, d1, o);
        d2 += __shfl_xor_sync(0xffffffffu, d2, o);
        d3 += __shfl_xor_sync(0xffffffffu, d3, o);
    }
    if (lane == 0) {
        bool mk = maskf[r] != 0.f;
        float dm[4] = {d0, d1, d2, d3};
        size_t base = (size_t)q * (HEADS * NKEY) + (size_t)n * GRP + w;
#pragma unroll
        for (int m = 0; m < 4; m++)
            dotp[base + (size_t)m * NKEY] = mk ? SCALE * (dm[m] + bd[m]) : -1e9f;
    }
}

// ---------------- K5: softmax over 48 keys ----------------
__global__ __launch_bounds__(256)
void k_softmax(float* __restrict__ d)
{
    int row = blockIdx.x * 8 + (threadIdx.x >> 5);
    int lane = threadIdx.x & 31;
    float* p = d + (size_t)row * NKEY;
    float v0 = p[lane];
    float v1 = (lane < 16) ? p[32 + lane] : -3.4e38f;
    float m = fmaxf(v0, v1);
#pragma unroll
    for (int o = 16; o > 0; o >>= 1) m = fmaxf(m, __shfl_xor_sync(0xffffffffu, m, o));
    float e0 = expf(v0 - m);
    float e1 = (lane < 16) ? expf(v1 - m) : 0.f;
    float s = e0 + e1;
#pragma unroll
    for (int o = 16; o > 0; o >>= 1) s += __shfl_xor_sync(0xffffffffu, s, o);
    float inv = 1.f / s;
    p[lane] = e0 * inv;
    if (lane < 16) p[32 + lane] = e1 * inv;
}

// ---------------- K6: weighted sum of LN(v), warp-per-group ----------------
__global__ __launch_bounds__(256)
void k_vacc(const float* __restrict__ vten, const float* __restrict__ att,
            const float* __restrict__ lng, const float* __restrict__ lnb,
            float* __restrict__ apre)
{
    __shared__ float sa[HEADS * NKEY];
    __shared__ float part[8][1024];
    int q = blockIdx.x, tid = threadIdx.x, lane = tid & 31, w = tid >> 5;
    if (tid < HEADS * NKEY) sa[tid] = att[(size_t)q * (HEADS * NKEY) + tid];
    float gg[8], bb[8];
#pragma unroll
    for (int j = 0; j < 8; j++) { gg[j] = lng[lane + 32 * j]; bb[j] = lnb[lane + 32 * j]; }
    __syncthreads();
    float acc[4][8] = {};
    for (int n = 0; n < NFR; n++) {
        const float* vr = vten + (((size_t)n * QLEN + q) * GRP + w) * 256;
        float vv[8];
        float s1 = 0.f, s2 = 0.f;
#pragma unroll
        for (int j = 0; j < 8; j++) {
            vv[j] = vr[lane + 32 * j];
            s1 += vv[j]; s2 += vv[j] * vv[j];
        }
#pragma unroll
        for (int o = 16; o > 0; o >>= 1) {
            s1 += __shfl_xor_sync(0xffffffffu, s1, o);
            s2 += __shfl_xor_sync(0xffffffffu, s2, o);
        }
        float mu = s1 * (1.f / 256.f);
        float rs = rsqrtf(s2 * (1.f / 256.f) - mu * mu + EPSLN);
        float aw0 = sa[0 * NKEY + n * 8 + w];
        float aw1 = sa[1 * NKEY + n * 8 + w];
        float aw2 = sa[2 * NKEY + n * 8 + w];
        float aw3 = sa[3 * NKEY + n * 8 + w];
#pragma unroll
        for (int j = 0; j < 8; j++) {
            float lv = (vv[j] - mu) * rs * gg[j] + bb[j];
            acc[0][j] += aw0 * lv;
            acc[1][j] += aw1 * lv;
            acc[2][j] += aw2 * lv;
            acc[3][j] += aw3 * lv;
        }
    }
#pragma unroll
    for (int m = 0; m < 4; m++)
#pragma unroll
        for (int j = 0; j < 8; j++)
            part[w][m * 256 + lane + 32 * j] = acc[m][j];
    __syncthreads();
#pragma unroll
    for (int m = 0; m < 4; m++) {
        float s = 0.f;
#pragma unroll
        for (int w8 = 0; w8 < 8; w8++) s += part[w8][m * 256 + tid];
        apre[(size_t)q * 1024 + m * 256 + tid] = s;
    }
}

// ---------------- K7: z = LN_pre(zp + skip^T) ----------------
__global__ __launch_bounds__(256)
void k_ln_skip(const float* __restrict__ zp, const float* __restrict__ skip,
               const float* __restrict__ g, const float* __restrict__ b,
               float* __restrict__ zln)
{
    __shared__ float red[16];
    int q = blockIdx.x, c = threadIdx.x;
    float v = zp[(size_t)q * 256 + c] + skip[(size_t)c * QLEN + q];
    float s1 = v, s2 = v * v;
    blockReduce2(s1, s2, red);
    float mu = s1 * (1.f / 256.f);
    float rs = rsqrtf(s2 * (1.f / 256.f) - mu * mu + EPSLN);
    zln[(size_t)q * 256 + c] = (v - mu) * rs * g[c] + b[c];
}

// ---------------- K8: out = LN_post(zln + hp), transposed store ----------------
__global__ __launch_bounds__(256)
void k_ln_out(const float* __restrict__ zln, const float* __restrict__ hp,
              const float* __restrict__ g, const float* __restrict__ b,
              float* __restrict__ out)
{
    __shared__ float red[16];
    int q = blockIdx.x, c = threadIdx.x;
    float v = zln[(size_t)q * 256 + c] + hp[(size_t)q * 256 + c];
    float s1 = v, s2 = v * v;
    blockReduce2(s1, s2, red);
    float mu = s1 * (1.f / 256.f);
    float rs = rsqrtf(s2 * (1.f / 256.f) - mu * mu + EPSLN);
    out[(size_t)c * QLEN + q] = (v - mu) * rs * g[c] + b[c];
}

// ---------------- host launch ----------------
extern "C" void kernel_launch(void* const* d_in, const int* in_sizes, int n_in,
                              void* d_out, int out_size)
{
    const float* q        = (const float*)d_in[0];
    const float* k        = (const float*)d_in[1];
    const float* v        = (const float*)d_in[2];
    const float* skip     = (const float*)d_in[3];
    const void*  mask     = d_in[4];
    const float* ln_q_g   = (const float*)d_in[5];
    const float* ln_q_b   = (const float*)d_in[6];
    const float* wq       = (const float*)d_in[7];
    const float* bq       = (const float*)d_in[8];
    const float* ln_k_g   = (const float*)d_in[9];
    const float* ln_k_b   = (const float*)d_in[10];
    const float* wk       = (const float*)d_in[11];
    const float* bk       = (const float*)d_in[12];
    const float* ln_v_g   = (const float*)d_in[13];
    const float* ln_v_b   = (const float*)d_in[14];
    const float* wv       = (const float*)d_in[15];
    const float* bv       = (const float*)d_in[16];
    const float* w_proj   = (const float*)d_in[17];
    const float* b_proj   = (const float*)d_in[18];
    const float* ln_pre_g = (const float*)d_in[19];
    const float* ln_pre_b = (const float*)d_in[20];
    const float* w_mlp1   = (const float*)d_in[21];
    const float* b_mlp1   = (const float*)d_in[22];
    const float* w_mlp2   = (const float*)d_in[23];
    const float* b_mlp2   = (const float*)d_in[24];
    const float* ln_post_g= (const float*)d_in[25];
    const float* ln_post_b= (const float*)d_in[26];
    float* out = (float*)d_out;

    float *qln, *qp, *t, *wkT, *dot, *apre, *av, *zp, *zln, *h1, *hp, *maskf;
    cudaGetSymbolAddress((void**)&qln,  g_qln);
    cudaGetSymbolAddress((void**)&qp,   g_qp);
    cudaGetSymbolAddress((void**)&t,    g_t);
    cudaGetSymbolAddress((void**)&wkT,  g_wkT);
    cudaGetSymbolAddress((void**)&dot,  g_dot);
    cudaGetSymbolAddress((void**)&apre, g_apre);
    cudaGetSymbolAddress((void**)&av,   g_av);
    cudaGetSymbolAddress((void**)&zp,   g_zp);
    cudaGetSymbolAddress((void**)&zln,  g_zln);
    cudaGetSymbolAddress((void**)&h1,   g_h1);
    cudaGetSymbolAddress((void**)&hp,   g_hp);
    cudaGetSymbolAddress((void**)&maskf,g_maskf);

    k_mask_detect<<<1, 256>>>((const unsigned char*)mask);
    k_mask_norm<<<(NFR * QLEN + 255) / 256, 256>>>(mask);
    k_q_ln<<<dim3(QLEN / 32, NFR), 256>>>(q, ln_q_g, ln_q_b, qln);
    k_tr256<<<dim3(8, 8), dim3(32, 8)>>>(wk, wkT);

    // qp = qln @ wq + bq  (24576 x 256 x 256)
    tgemm<<<dim3(2, 192, 1), 256>>>(R_TOT, 256, 256, qln, 256, 0,
                                    wq, 256, 0, bq, 0, qp, 256, 0, 0);
    // t_m = qp_m @ wkT_m  (24576 x 256, K=64), batched over heads
    tgemm<<<dim3(2, 192, 4), 256>>>(R_TOT, 256, 64, qp, 256, 64,
                                    wkT, 256, 64 * 256, nullptr, 0,
                                    t, 1024, 256, 0);
    k_dot<<<R_TOT, 256>>>(k, qp, t, bk, ln_k_g, ln_k_b, maskf, dot);
    k_softmax<<<QLEN * HEADS / 8, 256>>>(dot);
    k_vacc<<<QLEN, 256>>>(v, dot, ln_v_g, ln_v_b, apre);
    // a_m = apre_m @ wv_m + bv_m  (4096 x 64, K=256), batched over heads
    tgemm<<<dim3(1, 32, 4), 256>>>(QLEN, 64, 256, apre, 1024, 256,
                                   wv, 256, 64, bv, 64, av, 256, 64, 0);
    // zp = av @ w_proj + b_proj
    tgemm<<<dim3(2, 32, 1), 256>>>(QLEN, 256, 256, av, 256, 0,
                                   w_proj, 256, 0, b_proj, 0, zp, 256, 0, 0);
    k_ln_skip<<<QLEN, 256>>>(zp, skip, ln_pre_g, ln_pre_b, zln);
    // h1 = gelu(zln @ w_mlp1 + b_mlp1)
    tgemm<<<dim3(4, 32, 1), 256>>>(QLEN, 512, 256, zln, 256, 0,
                                   w_mlp1, 512, 0, b_mlp1, 0, h1, 512, 0, 1);
    // hp = h1 @ w_mlp2 + b_mlp2
    tgemm<<<dim3(2, 32, 1), 256>>>(QLEN, 256, 512, h1, 512, 0,
                                   w_mlp2, 256, 0, b_mlp2, 0, hp, 256, 0, 0);
    k_ln_out<<<QLEN, 256>>>(zln, hp, ln_post_g, ln_post_b, out);
}

// round 5
// speedup vs baseline: 2.4259x; 1.1111x over previous
#include <cuda_runtime.h>
#include <cuda_bf16.h>
#include <cuda_fp16.h>
#include <math.h>
#include <stdint.h>

// ---------------- problem constants ----------------
#define QLEN   4096
#define NFR    6
#define GRP    8
#define DIMC   256
#define HEADS  4
#define DH     64
#define NKEY   48
#define R_TOT  (NFR*QLEN)
#define EPSLN  1e-5f
#define SCALE  0.125f

// ---------------- scratch ----------------
__device__ float    g_qln [R_TOT*DIMC];
__device__ float    g_qp  [R_TOT*DIMC];
__device__ __half   g_t   [R_TOT*1024];
__device__ float    g_dot [QLEN*HEADS*NKEY];
__device__ float    g_apre[QLEN*1024];
__device__ float    g_av  [QLEN*DIMC];
__device__ float    g_zp  [QLEN*DIMC];
__device__ float    g_zln [QLEN*DIMC];
__device__ float    g_h1  [QLEN*512];
__device__ float    g_hp  [QLEN*DIMC];
__device__ int      g_mmode;
__device__ float    g_maskf[R_TOT];
// packed bf16 hi/lo weights, layout [z][N][K/2] uint32 (pair = cols k,k+1 of B^T row n)
__device__ uint32_t g_pwq_h[256*128],  g_pwq_l[256*128];
__device__ uint32_t g_pwk_h[4*256*32], g_pwk_l[4*256*32];
__device__ uint32_t g_pwv_h[4*64*128], g_pwv_l[4*64*128];
__device__ uint32_t g_pwp_h[256*128],  g_pwp_l[256*128];
__device__ uint32_t g_pw1_h[512*128],  g_pw1_l[512*128];
__device__ uint32_t g_pw2_h[256*256],  g_pw2_l[256*256];

// ---------------- helpers ----------------
__device__ __forceinline__ void blockReduce2(float& s1, float& s2, float* red)
{
    int lane = threadIdx.x & 31, w = threadIdx.x >> 5;
#pragma unroll
    for (int o = 16; o > 0; o >>= 1) {
        s1 += __shfl_xor_sync(0xffffffffu, s1, o);
        s2 += __shfl_xor_sync(0xffffffffu, s2, o);
    }
    if (lane == 0) { red[w] = s1; red[8 + w] = s2; }
    __syncthreads();
    float a = 0.f, b = 0.f;
#pragma unroll
    for (int j = 0; j < 8; j++) { a += red[j]; b += red[8 + j]; }
    s1 = a; s2 = b;
    __syncthreads();
}

__device__ __forceinline__ uint32_t pack_hi(float x0, float x1)
{
    __nv_bfloat162 h = __floats2bfloat162_rn(x0, x1);
    return *reinterpret_cast<uint32_t*>(&h);
}
__device__ __forceinline__ uint32_t pack_lo(float x0, float x1, uint32_t hi)
{
    __nv_bfloat162 h = *reinterpret_cast<__nv_bfloat162*>(&hi);
    float r0 = x0 - __bfloat162float(h.x);
    float r1 = x1 - __bfloat162float(h.y);
    __nv_bfloat162 l = __floats2bfloat162_rn(r0, r1);
    return *reinterpret_cast<uint32_t*>(&l);
}

__device__ __forceinline__ void mma16(float* c, const uint32_t* a, const uint32_t* b)
{
    asm volatile(
        "mma.sync.aligned.m16n8k16.row.col.f32.bf16.bf16.f32 "
        "{%0,%1,%2,%3}, {%4,%5,%6,%7}, {%8,%9}, {%0,%1,%2,%3};"
        : "+f"(c[0]), "+f"(c[1]), "+f"(c[2]), "+f"(c[3])
        : "r"(a[0]), "r"(a[1]), "r"(a[2]), "r"(a[3]), "r"(b[0]), "r"(b[1]));
}

// ---------------- weight pack: dst[z][n][kp] = bf16x2(src[z*zoff + n*sn + (2kp(+1))*sk]) ----------------
__global__ void k_pack(const float* __restrict__ src, int sn, int sk, int zoff,
                       int N, int Kp, uint32_t* __restrict__ dh, uint32_t* __restrict__ dl)
{
    int z = blockIdx.y;
    const float* s = src + (size_t)z * zoff;
    size_t base = (size_t)z * N * Kp;
    int i = blockIdx.x * 256 + threadIdx.x;
    if (i >= N * Kp) return;
    int n = i / Kp, kp = i - n * Kp;
    float x0 = s[(size_t)n * sn + (size_t)(2 * kp) * sk];
    float x1 = s[(size_t)n * sn + (size_t)(2 * kp + 1) * sk];
    uint32_t h = pack_hi(x0, x1);
    dh[base + i] = h;
    dl[base + i] = pack_lo(x0, x1, h);
}

// ---------------- mask dtype detect + normalize ----------------
__global__ void k_mask_detect(const unsigned char* __restrict__ m)
{
    __shared__ int fA, fB;
    if (threadIdx.x == 0) { fA = 0; fB = 0; }
    __syncthreads();
    for (int i = threadIdx.x; i < NFR * QLEN; i += 256) {
        unsigned char b = m[i];
        if (b == 1) {
            if ((i & 3) == 0) fA = 1;
            else              fB = 1;
        }
    }
    __syncthreads();
    if (threadIdx.x == 0) g_mmode = fB ? 0 : (fA ? 1 : 2);
}

__global__ void k_mask_norm(const void* __restrict__ m)
{
    int i = blockIdx.x * 256 + threadIdx.x;
    if (i >= NFR * QLEN) return;
    int mode = g_mmode;
    float r;
    if (mode == 0)      r = (((const unsigned char*)m)[i] != 0) ? 1.f : 0.f;
    else if (mode == 1) r = (((const int*)m)[i] != 0) ? 1.f : 0.f;
    else                r = (((const float*)m)[i] != 0.f) ? 1.f : 0.f;
    g_maskf[i] = r;
}

// ---------------- K1: transpose q + LayerNorm ----------------
__global__ __launch_bounds__(256)
void k_q_ln(const float* __restrict__ q, const float* __restrict__ g,
            const float* __restrict__ b, float* __restrict__ out)
{
    __shared__ float tile[256][33];
    __shared__ float s_mu[32], s_rs[32];
    __shared__ float s_part[2][8][32];
    int n  = blockIdx.y;
    int p0 = blockIdx.x * 32;
    int t  = threadIdx.x;
    int px = t & 31, cy = t >> 5;
    const float* qn = q + (size_t)n * DIMC * QLEN;
    float s1 = 0.f, s2 = 0.f;
    for (int c = cy; c < DIMC; c += 8) {
        float v = qn[(size_t)c * QLEN + p0 + px];
        tile[c][px] = v;
        s1 += v; s2 += v * v;
    }
    s_part[0][cy][px] = s1; s_part[1][cy][px] = s2;
    __syncthreads();
    if (cy == 0) {
        float a = 0.f, bb = 0.f;
#pragma unroll
        for (int j = 0; j < 8; j++) { a += s_part[0][j][px]; bb += s_part[1][j][px]; }
        float mu = a * (1.f / 256.f);
        float var = bb * (1.f / 256.f) - mu * mu;
        s_mu[px] = mu; s_rs[px] = rsqrtf(var + EPSLN);
    }
    __syncthreads();
    float gg = g[t], bv = b[t];
    float* orow = out + ((size_t)n * QLEN + p0) * DIMC;
#pragma unroll 4
    for (int pp = 0; pp < 32; pp++) {
        float v = tile[t][pp];
        orow[(size_t)pp * DIMC + t] = (v - s_mu[pp]) * s_rs[pp] * gg + bv;
    }
}

// ---------------- bf16x2 emulated-fp32 tensor GEMM ----------------
// C[M,N] = A[M,K] @ B[K,N] (+bias). A fp32 row-major. B pre-packed as
// [z][N][K/2] hi/lo uint32 (pairs along k). M%128==0, K%32==0.
// outfmt: 0 = fp32, 1 = fp32 + exact gelu, 2 = fp16.
__global__ __launch_bounds__(256)
void bgemm(int M, int N, int K,
           const float* __restrict__ A, int lda, long aoz,
           const uint32_t* __restrict__ Bh, const uint32_t* __restrict__ Bl, long bzs,
           const float* __restrict__ bias, int bioz,
           void* __restrict__ Cv, int ldc, long coz, int outfmt)
{
    __shared__ uint32_t Ah[128][20], Al[128][20];
    __shared__ uint32_t Bhs[128][20], Bls[128][20];

    int z = blockIdx.z;
    A  += (size_t)z * aoz;
    Bh += (size_t)z * bzs;
    Bl += (size_t)z * bzs;
    if (bias) bias += (size_t)z * bioz;
    int Kp = K >> 1;

    int tid = threadIdx.x, lane = tid & 31, wid = tid >> 5;
    int wm = wid & 3, wn = wid >> 2;
    int g = lane >> 2, t = lane & 3;
    int bm = blockIdx.y * 128, bn = blockIdx.x * 128;

    float acc[2][8][4] = {};

    int arow = tid >> 1;
    int af0  = (tid & 1) << 4;          // 0 or 16 (floats)
    int brow = tid >> 1;
    int bp0  = (tid & 1) << 3;          // 0 or 8 (pairs)

    const float* Abase = A + (size_t)(bm + arow) * lda + af0;
    bool bvalid = (bn + brow) < N;
    const uint32_t* Bhb = Bh + (size_t)(bn + brow) * Kp + bp0;
    const uint32_t* Blb = Bl + (size_t)(bn + brow) * Kp + bp0;

    for (int k0 = 0; k0 < K; k0 += 32) {
        // A fill: 16 floats -> 8 hi/lo pairs, split once here
#pragma unroll
        for (int x = 0; x < 4; x++) {
            float4 v = *(const float4*)(Abase + k0 + x * 4);
            int kp = (af0 >> 1) + x * 2;
            uint32_t h0 = pack_hi(v.x, v.y);
            uint32_t h1 = pack_hi(v.z, v.w);
            Ah[arow][kp]     = h0;
            Ah[arow][kp + 1] = h1;
            Al[arow][kp]     = pack_lo(v.x, v.y, h0);
            Al[arow][kp + 1] = pack_lo(v.z, v.w, h1);
        }
        // B fill: straight uint4 copies of pre-packed weights
#pragma unroll
        for (int x = 0; x < 2; x++) {
            uint4 hv = make_uint4(0u, 0u, 0u, 0u), lv = hv;
            if (bvalid) {
                hv = *(const uint4*)(Bhb + (k0 >> 1) + x * 4);
                lv = *(const uint4*)(Blb + (k0 >> 1) + x * 4);
            }
            int kp = bp0 + x * 4;
            *(uint4*)&Bhs[brow][kp] = hv;
            *(uint4*)&Bls[brow][kp] = lv;
        }
        __syncthreads();

#pragma unroll
        for (int s = 0; s < 2; s++) {
            int sb = s * 8;
            uint32_t ah[2][4], al[2][4];
#pragma unroll
            for (int i = 0; i < 2; i++) {
                int r = wm * 32 + i * 16;
                ah[i][0] = Ah[r + g][sb + t];
                ah[i][1] = Ah[r + 8 + g][sb + t];
                ah[i][2] = Ah[r + g][sb + t + 4];
                ah[i][3] = Ah[r + 8 + g][sb + t + 4];
                al[i][0] = Al[r + g][sb + t];
                al[i][1] = Al[r + 8 + g][sb + t];
                al[i][2] = Al[r + g][sb + t + 4];
                al[i][3] = Al[r + 8 + g][sb + t + 4];
            }
#pragma unroll
            for (int j = 0; j < 8; j++) {
                int nc = wn * 64 + j * 8 + g;
                uint32_t bh[2], bl[2];
                bh[0] = Bhs[nc][sb + t];
                bh[1] = Bhs[nc][sb + t + 4];
                bl[0] = Bls[nc][sb + t];
                bl[1] = Bls[nc][sb + t + 4];
#pragma unroll
                for (int i = 0; i < 2; i++) {
                    mma16(acc[i][j], ah[i], bh);
                    mma16(acc[i][j], al[i], bh);
                    mma16(acc[i][j], ah[i], bl);
                }
            }
        }
        __syncthreads();
    }

    // epilogue
#pragma unroll
    for (int i = 0; i < 2; i++) {
        int r0 = bm + wm * 32 + i * 16 + g;
#pragma unroll
        for (int j = 0; j < 8; j++) {
            int c0 = bn + wn * 64 + j * 8 + t * 2;
            if (c0 >= N) continue;
            float b0v = bias ? bias[c0] : 0.f;
            float b1v = bias ? bias[c0 + 1] : 0.f;
            float v0 = acc[i][j][0] + b0v;
            float v1 = acc[i][j][1] + b1v;
            float v2 = acc[i][j][2] + b0v;
            float v3 = acc[i][j][3] + b1v;
            if (outfmt == 1) {
                v0 = 0.5f * v0 * (1.f + erff(v0 * 0.70710678118654752f));
                v1 = 0.5f * v1 * (1.f + erff(v1 * 0.70710678118654752f));
                v2 = 0.5f * v2 * (1.f + erff(v2 * 0.70710678118654752f));
                v3 = 0.5f * v3 * (1.f + erff(v3 * 0.70710678118654752f));
            }
            if (outfmt == 2) {
                __half* Ch = (__half*)Cv + (size_t)z * coz;
                *(__half2*)&Ch[(size_t)r0 * ldc + c0]       = __floats2half2_rn(v0, v1);
                *(__half2*)&Ch[(size_t)(r0 + 8) * ldc + c0] = __floats2half2_rn(v2, v3);
            } else {
                float* C = (float*)Cv + (size_t)z * coz;
                *(float2*)&C[(size_t)r0 * ldc + c0]       = make_float2(v0, v1);
                *(float2*)&C[(size_t)(r0 + 8) * ldc + c0] = make_float2(v2, v3);
            }
        }
    }
}

// ---------------- K4: attention scores ----------------
__global__ __launch_bounds__(256)
void k_dot(const float* __restrict__ kten, const float* __restrict__ qp,
           const __half* __restrict__ tg, const float* __restrict__ bk,
           const float* __restrict__ lng, const float* __restrict__ lnb,
           const float* __restrict__ maskf, float* __restrict__ dotp)
{
    int r = blockIdx.x;
    int n = r >> 12, q = r & 4095;
    int tid = threadIdx.x, lane = tid & 31, w = tid >> 5;
    __shared__ float ts[1024];
    __shared__ float bd[4];
    __shared__ float sg[256], sb[256];
    const __half* trow = tg + (size_t)r * 1024;
#pragma unroll
    for (int i = 0; i < 4; i++) ts[tid + 256 * i] = __half2float(trow[tid + 256 * i]);
    sg[tid] = lng[tid]; sb[tid] = lnb[tid];
    if (w < 4) {
        const float* qpr = qp + (size_t)r * 256 + w * 64;
        const float* bkr = bk + w * 64;
        float p = qpr[lane] * bkr[lane] + qpr[lane + 32] * bkr[lane + 32];
#pragma unroll
        for (int o = 16; o > 0; o >>= 1) p += __shfl_xor_sync(0xffffffffu, p, o);
        if (lane == 0) bd[w] = p;
    }
    __syncthreads();
    const float* krow = kten + ((size_t)r * GRP + w) * 256;
    float v[8];
    float s1 = 0.f, s2 = 0.f;
#pragma unroll
    for (int j = 0; j < 8; j++) {
        v[j] = krow[lane + 32 * j];
        s1 += v[j]; s2 += v[j] * v[j];
    }
#pragma unroll
    for (int o = 16; o > 0; o >>= 1) {
        s1 += __shfl_xor_sync(0xffffffffu, s1, o);
        s2 += __shfl_xor_sync(0xffffffffu, s2, o);
    }
    float mu = s1 * (1.f / 256.f);
    float rs = rsqrtf(s2 * (1.f / 256.f) - mu * mu + EPSLN);
    float d0 = 0.f, d1 = 0.f, d2 = 0.f, d3 = 0.f;
#pragma unroll
    for (int j = 0; j < 8; j++) {
        int c = lane + 32 * j;
        float lv = (v[j] - mu) * rs * sg[c] + sb[c];
        d0 += lv * ts[c];
        d1 += lv * ts[256 + c];
        d2 += lv * ts[512 + c];
        d3 += lv * ts[768 + c];
    }
#pragma unroll
    for (int o = 16; o > 0; o >>= 1) {
        d0 += __shfl_xor_sync(0xffffffffu, d0, o);
        d1 += __shfl_xor_sync(0xffffffffu, d1, o);
        d2 += __shfl_xor_sync(0xffffffffu, d2, o);
        d3 += __shfl_xor_sync(0xffffffffu, d3, o);
    }
    if (lane == 0) {
        bool mk = maskf[r] != 0.f;
        float dm[4] = {d0, d1, d2, d3};
        size_t base = (size_t)q * (HEADS * NKEY) + (size_t)n * GRP + w;
#pragma unroll
        for (int m = 0; m < 4; m++)
            dotp[base + (size_t)m * NKEY] = mk ? SCALE * (dm[m] + bd[m]) : -1e9f;
    }
}

// ---------------- K5: softmax over 48 keys ----------------
__global__ __launch_bounds__(256)
void k_softmax(float* __restrict__ d)
{
    int row = blockIdx.x * 8 + (threadIdx.x >> 5);
    int lane = threadIdx.x & 31;
    float* p = d + (size_t)row * NKEY;
    float v0 = p[lane];
    float v1 = (lane < 16) ? p[32 + lane] : -3.4e38f;
    float m = fmaxf(v0, v1);
#pragma unroll
    for (int o = 16; o > 0; o >>= 1) m = fmaxf(m, __shfl_xor_sync(0xffffffffu, m, o));
    float e0 = expf(v0 - m);
    float e1 = (lane < 16) ? expf(v1 - m) : 0.f;
    float s = e0 + e1;
#pragma unroll
    for (int o = 16; o > 0; o >>= 1) s += __shfl_xor_sync(0xffffffffu, s, o);
    float inv = 1.f / s;
    p[lane] = e0 * inv;
    if (lane < 16) p[32 + lane] = e1 * inv;
}

// ---------------- K6: weighted sum of LN(v), warp-per-group ----------------
__global__ __launch_bounds__(256)
void k_vacc(const float* __restrict__ vten, const float* __restrict__ att,
            const float* __restrict__ lng, const float* __restrict__ lnb,
            float* __restrict__ apre)
{
    __shared__ float sa[HEADS * NKEY];
    __shared__ float part[8][1024];
    int q = blockIdx.x, tid = threadIdx.x, lane = tid & 31, w = tid >> 5;
    if (tid < HEADS * NKEY) sa[tid] = att[(size_t)q * (HEADS * NKEY) + tid];
    float gg[8], bb[8];
#pragma unroll
    for (int j = 0; j < 8; j++) { gg[j] = lng[lane + 32 * j]; bb[j] = lnb[lane + 32 * j]; }
    __syncthreads();
    float acc[4][8] = {};
    for (int n = 0; n < NFR; n++) {
        const float* vr = vten + (((size_t)n * QLEN + q) * GRP + w) * 256;
        float vv[8];
        float s1 = 0.f, s2 = 0.f;
#pragma unroll
        for (int j = 0; j < 8; j++) {
            vv[j] = vr[lane + 32 * j];
            s1 += vv[j]; s2 += vv[j] * vv[j];
        }
#pragma unroll
        for (int o = 16; o > 0; o >>= 1) {
            s1 += __shfl_xor_sync(0xffffffffu, s1, o);
            s2 += __shfl_xor_sync(0xffffffffu, s2, o);
        }
        float mu = s1 * (1.f / 256.f);
        float rs = rsqrtf(s2 * (1.f / 256.f) - mu * mu + EPSLN);
        float aw0 = sa[0 * NKEY + n * 8 + w];
        float aw1 = sa[1 * NKEY + n * 8 + w];
        float aw2 = sa[2 * NKEY + n * 8 + w];
        float aw3 = sa[3 * NKEY + n * 8 + w];
#pragma unroll
        for (int j = 0; j < 8; j++) {
            float lv = (vv[j] - mu) * rs * gg[j] + bb[j];
            acc[0][j] += aw0 * lv;
            acc[1][j] += aw1 * lv;
            acc[2][j] += aw2 * lv;
            acc[3][j] += aw3 * lv;
        }
    }
#pragma unroll
    for (int m = 0; m < 4; m++)
#pragma unroll
        for (int j = 0; j < 8; j++)
            part[w][m * 256 + lane + 32 * j] = acc[m][j];
    __syncthreads();
#pragma unroll
    for (int m = 0; m < 4; m++) {
        float s = 0.f;
#pragma unroll
        for (int w8 = 0; w8 < 8; w8++) s += part[w8][m * 256 + tid];
        apre[(size_t)q * 1024 + m * 256 + tid] = s;
    }
}

// ---------------- K7: z = LN_pre(zp + skip^T) ----------------
__global__ __launch_bounds__(256)
void k_ln_skip(const float* __restrict__ zp, const float* __restrict__ skip,
               const float* __restrict__ g, const float* __restrict__ b,
               float* __restrict__ zln)
{
    __shared__ float red[16];
    int q = blockIdx.x, c = threadIdx.x;
    float v = zp[(size_t)q * 256 + c] + skip[(size_t)c * QLEN + q];
    float s1 = v, s2 = v * v;
    blockReduce2(s1, s2, red);
    float mu = s1 * (1.f / 256.f);
    float rs = rsqrtf(s2 * (1.f / 256.f) - mu * mu + EPSLN);
    zln[(size_t)q * 256 + c] = (v - mu) * rs * g[c] + b[c];
}

// ---------------- K8: out = LN_post(zln + hp), transposed store ----------------
__global__ __launch_bounds__(256)
void k_ln_out(const float* __restrict__ zln, const float* __restrict__ hp,
              const float* __restrict__ g, const float* __restrict__ b,
              float* __restrict__ out)
{
    __shared__ float red[16];
    int q = blockIdx.x, c = threadIdx.x;
    float v = zln[(size_t)q * 256 + c] + hp[(size_t)q * 256 + c];
    float s1 = v, s2 = v * v;
    blockReduce2(s1, s2, red);
    float mu = s1 * (1.f / 256.f);
    float rs = rsqrtf(s2 * (1.f / 256.f) - mu * mu + EPSLN);
    out[(size_t)c * QLEN + q] = (v - mu) * rs * g[c] + b[c];
}

// ---------------- host launch ----------------
extern "C" void kernel_launch(void* const* d_in, const int* in_sizes, int n_in,
                              void* d_out, int out_size)
{
    const float* q        = (const float*)d_in[0];
    const float* k        = (const float*)d_in[1];
    const float* v        = (const float*)d_in[2];
    const float* skip     = (const float*)d_in[3];
    const void*  mask     = d_in[4];
    const float* ln_q_g   = (const float*)d_in[5];
    const float* ln_q_b   = (const float*)d_in[6];
    const float* wq       = (const float*)d_in[7];
    const float* bq       = (const float*)d_in[8];
    const float* ln_k_g   = (const float*)d_in[9];
    const float* ln_k_b   = (const float*)d_in[10];
    const float* wk       = (const float*)d_in[11];
    const float* bk       = (const float*)d_in[12];
    const float* ln_v_g   = (const float*)d_in[13];
    const float* ln_v_b   = (const float*)d_in[14];
    const float* wv       = (const float*)d_in[15];
    const float* bv       = (const float*)d_in[16];
    const float* w_proj   = (const float*)d_in[17];
    const float* b_proj   = (const float*)d_in[18];
    const float* ln_pre_g = (const float*)d_in[19];
    const float* ln_pre_b = (const float*)d_in[20];
    const float* w_mlp1   = (const float*)d_in[21];
    const float* b_mlp1   = (const float*)d_in[22];
    const float* w_mlp2   = (const float*)d_in[23];
    const float* b_mlp2   = (const float*)d_in[24];
    const float* ln_post_g= (const float*)d_in[25];
    const float* ln_post_b= (const float*)d_in[26];
    float* out = (float*)d_out;

    float *qln, *qp, *dot, *apre, *av, *zp, *zln, *h1, *hp, *maskf;
    __half* t;
    uint32_t *pwq_h, *pwq_l, *pwk_h, *pwk_l, *pwv_h, *pwv_l;
    uint32_t *pwp_h, *pwp_l, *pw1_h, *pw1_l, *pw2_h, *pw2_l;
    cudaGetSymbolAddress((void**)&qln,  g_qln);
    cudaGetSymbolAddress((void**)&qp,   g_qp);
    cudaGetSymbolAddress((void**)&t,    g_t);
    cudaGetSymbolAddress((void**)&dot,  g_dot);
    cudaGetSymbolAddress((void**)&apre, g_apre);
    cudaGetSymbolAddress((void**)&av,   g_av);
    cudaGetSymbolAddress((void**)&zp,   g_zp);
    cudaGetSymbolAddress((void**)&zln,  g_zln);
    cudaGetSymbolAddress((void**)&h1,   g_h1);
    cudaGetSymbolAddress((void**)&hp,   g_hp);
    cudaGetSymbolAddress((void**)&maskf,g_maskf);
    cudaGetSymbolAddress((void**)&pwq_h, g_pwq_h); cudaGetSymbolAddress((void**)&pwq_l, g_pwq_l);
    cudaGetSymbolAddress((void**)&pwk_h, g_pwk_h); cudaGetSymbolAddress((void**)&pwk_l, g_pwk_l);
    cudaGetSymbolAddress((void**)&pwv_h, g_pwv_h); cudaGetSymbolAddress((void**)&pwv_l, g_pwv_l);
    cudaGetSymbolAddress((void**)&pwp_h, g_pwp_h); cudaGetSymbolAddress((void**)&pwp_l, g_pwp_l);
    cudaGetSymbolAddress((void**)&pw1_h, g_pw1_h); cudaGetSymbolAddress((void**)&pw1_l, g_pw1_l);
    cudaGetSymbolAddress((void**)&pw2_h, g_pw2_h); cudaGetSymbolAddress((void**)&pw2_l, g_pw2_l);

    k_mask_detect<<<1, 256>>>((const unsigned char*)mask);
    k_mask_norm<<<(NFR * QLEN + 255) / 256, 256>>>(mask);
    k_q_ln<<<dim3(QLEN / 32, NFR), 256>>>(q, ln_q_g, ln_q_b, qln);

    // pack weights (B^T, bf16 hi/lo pairs along k)
    k_pack<<<dim3(128, 1), 256>>>(wq,     1, 256, 0,  256, 128, pwq_h, pwq_l);
    k_pack<<<dim3(32, 4),  256>>>(wk,   256,   1, 64, 256,  32, pwk_h, pwk_l);
    k_pack<<<dim3(32, 4),  256>>>(wv,     1, 256, 64,  64, 128, pwv_h, pwv_l);
    k_pack<<<dim3(128, 1), 256>>>(w_proj, 1, 256, 0,  256, 128, pwp_h, pwp_l);
    k_pack<<<dim3(256, 1), 256>>>(w_mlp1, 1, 512, 0,  512, 128, pw1_h, pw1_l);
    k_pack<<<dim3(256, 1), 256>>>(w_mlp2, 1, 256, 0,  256, 256, pw2_h, pw2_l);

    // qp = qln @ wq + bq  (24576 x 256 x 256)
    bgemm<<<dim3(2, 192, 1), 256>>>(R_TOT, 256, 256, qln, 256, 0,
                                    pwq_h, pwq_l, 0, bq, 0, qp, 256, 0, 0);
    // t_m = qp_m @ wk_m^T (24576 x 256, K=64), batched over heads, fp16 out
    bgemm<<<dim3(2, 192, 4), 256>>>(R_TOT, 256, 64, qp, 256, 64,
                                    pwk_h, pwk_l, 256 * 32, nullptr, 0,
                                    t, 1024, 256, 2);
    k_dot<<<R_TOT, 256>>>(k, qp, t, bk, ln_k_g, ln_k_b, maskf, dot);
    k_softmax<<<QLEN * HEADS / 8, 256>>>(dot);
    k_vacc<<<QLEN, 256>>>(v, dot, ln_v_g, ln_v_b, apre);
    // a_m = apre_m @ wv_m + bv_m  (4096 x 64, K=256), batched over heads
    bgemm<<<dim3(1, 32, 4), 256>>>(QLEN, 64, 256, apre, 1024, 256,
                                   pwv_h, pwv_l, 64 * 128, bv, 64, av, 256, 64, 0);
    // zp = av @ w_proj + b_proj
    bgemm<<<dim3(2, 32, 1), 256>>>(QLEN, 256, 256, av, 256, 0,
                                   pwp_h, pwp_l, 0, b_proj, 0, zp, 256, 0, 0);
    k_ln_skip<<<QLEN, 256>>>(zp, skip, ln_pre_g, ln_pre_b, zln);
    // h1 = gelu(zln @ w_mlp1 + b_mlp1)
    bgemm<<<dim3(4, 32, 1), 256>>>(QLEN, 512, 256, zln, 256, 0,
                                   pw1_h, pw1_l, 0, b_mlp1, 0, h1, 512, 0, 1);
    // hp = h1 @ w_mlp2 + b_mlp2
    bgemm<<<dim3(2, 32, 1), 256>>>(QLEN, 256, 512, h1, 512, 0,
                                   pw2_h, pw2_l, 0, b_mlp2, 0, hp, 256, 0, 0);
    k_ln_out<<<QLEN, 256>>>(zln, hp, ln_post_g, ln_post_b, out);
}